// round 17
// baseline (speedup 1.0000x reference)
#include <cuda_runtime.h>
#include <cstdint>
#include <cstddef>

#define Bsz  64
#define Hd   512
#define Tlen 512
#define G4H  2048
#define Ed   256
#define NCTA 128
#define NTHR 512
#define HB   (Hd * Bsz)
#define PPAD 18

typedef unsigned long long ull;

// ---------------- device scratch (static, allowed) ----------------
__device__ __align__(256) float g_xg[(size_t)Tlen * G4H * Bsz];  // 256 MB
__device__ __align__(256) float g_h0[2 * HB];
__device__ __align__(256) float g_h1[2 * HB];
__device__ unsigned g_bar1;   // monotonic arrive counters (reset by kzero each launch)
__device__ unsigned g_bar2;

// ---------------- packed f32x2 helpers ----------------
__device__ __forceinline__ ull pk2f(float x) {
    ull r; asm("mov.b64 %0, {%1, %1};" : "=l"(r) : "f"(x)); return r;
}
__device__ __forceinline__ void ffma2(ull& a, ull h, ull w) {
    asm("fma.rn.f32x2 %0, %1, %2, %0;" : "+l"(a) : "l"(h), "l"(w));
}
__device__ __forceinline__ void up2(ull v, float& x, float& y) {
    unsigned lo, hi;
    asm("mov.b64 {%0, %1}, %2;" : "=r"(lo), "=r"(hi) : "l"(v));
    x = __uint_as_float(lo); y = __uint_as_float(hi);
}
__device__ __forceinline__ float sigm(float x) {
    return __fdividef(1.f, 1.f + __expf(-x));
}
__device__ __forceinline__ float tanh_fast(float x) {
    float e = __expf(2.f * x);
    return 1.f - __fdividef(2.f, e + 1.f);   // saturates to +/-1, NaN-free
}

// ---------------- split grid barrier: monotonic release/acquire ----------------
__device__ __forceinline__ void bar_arrive(unsigned* ctr) {
    if (threadIdx.x == 0)
        asm volatile("red.release.gpu.global.add.u32 [%0], 1;" :: "l"(ctr) : "memory");
}
__device__ __forceinline__ void bar_wait(unsigned* ctr, unsigned target) {
    if (threadIdx.x == 0) {
        unsigned v;
        do {
            asm volatile("ld.acquire.gpu.global.u32 %0, [%1];" : "=r"(v) : "l"(ctr) : "memory");
        } while (v < target);
    }
    __syncthreads();
}

// =================================================================
// Kernel A: Xg[t][row][b] = b0[row] + sum_e emb[x[b,t],e] * Wih0[row,e]
// (unchanged, proven)
// =================================================================
__global__ void __launch_bounds__(256) kA(const int* __restrict__ x,
                                          const float* __restrict__ emb,
                                          const float* __restrict__ Wih0,
                                          const float* __restrict__ b0) {
    __shared__ float ws[64 * 33];
    __shared__ float xs2[32 * 66];
    __shared__ int   xr[64];
    const int tid = threadIdx.x;
    const int t   = blockIdx.x;
    const int rb  = blockIdx.y * 64;
    if (tid < 64) xr[tid] = x[tid * Tlen + t];
    __syncthreads();

    ull accA[4], accB[4];
#pragma unroll
    for (int j = 0; j < 4; j++) { accA[j] = 0ull; accB[j] = 0ull; }
    const int r4 = tid >> 4;
    const int q4 = (tid & 15) * 4;

    for (int ec = 0; ec < Ed; ec += 32) {
#pragma unroll
        for (int i = 0; i < 8; i++) {
            int idx = tid + i * 256;
            int a = idx >> 5, e = idx & 31;
            ws[a * 33 + e] = Wih0[(rb + a) * Ed + ec + e];
            xs2[e * 66 + a] = emb[(size_t)xr[a] * Ed + ec + e];
        }
        __syncthreads();
#pragma unroll 8
        for (int e = 0; e < 32; e++) {
            ull x01 = *(const ull*)&xs2[e * 66 + q4];
            ull x23 = *(const ull*)&xs2[e * 66 + q4 + 2];
#pragma unroll
            for (int j = 0; j < 4; j++) {
                ull w2 = pk2f(ws[(r4 * 4 + j) * 33 + e]);
                ffma2(accA[j], x01, w2);
                ffma2(accB[j], x23, w2);
            }
        }
        __syncthreads();
    }
#pragma unroll
    for (int j = 0; j < 4; j++) {
        int row = rb + r4 * 4 + j;
        float bv = b0[row];
        float4 o;
        up2(accA[j], o.x, o.y);
        up2(accB[j], o.z, o.w);
        o.x += bv; o.y += bv; o.z += bv; o.w += bv;
        *(float4*)(g_xg + ((size_t)t * G4H + row) * Bsz + q4) = o;
    }
}

// =================================================================
__global__ void kzero() {
    int i = blockIdx.x * 256 + threadIdx.x;   // grid 256 -> 65536 = 2*HB
    g_h0[i] = 0.f;
    g_h1[i] = 0.f;
    if (i == 0) { g_bar1 = 0u; g_bar2 = 0u; }
}

// =================================================================
// Persistent recurrent kernel: 128 CTAs x 512 threads (16 warps).
// R8-proven schedule; warp = (kg 0..7, batch-half). Thread covers all
// 16 gate rows (8 packed row-pairs) x 1 batch over a 64-k slice.
// Weight row-pairs broadcast from smem (4 LDS.128/k), h scalar LDG.32
// with depth-16 ring (unroll 16 -> static idx). 8 partials per gate.
// smem: wT0[512][16] | wT1[1024][16] | pbuf[8][64][PPAD] = 135KB
// =================================================================
#define SM_WT0  0
#define SM_WT1  8192
#define SM_PBUF 24576
#define SM_TOTF (24576 + 8 * 64 * PPAD)
#define SMEMB   (SM_TOTF * 4)

// acc[rp] = packed rows (2rp, 2rp+1) for this thread's batch
template <int NK>
__device__ __forceinline__ void gemm3(ull (&acc)[8], const float* wT, int kw0,
                                      const float* __restrict__ hsrc, int kh0,
                                      int b) {
    const float* hp = hsrc + b;
    float hr[16];
#pragma unroll
    for (int j = 0; j < 16; j++) hr[j] = __ldcg(hp + (size_t)(kh0 + j) * 64);
#pragma unroll 16
    for (int i = 0; i < NK; i++) {
        float hc = hr[i & 15];
        if (i + 16 < NK) hr[i & 15] = __ldcg(hp + (size_t)(kh0 + i + 16) * 64);
        const ulonglong2* wp = (const ulonglong2*)(wT + (kw0 + i) * 16);
        ulonglong2 wA = wp[0];        // rows 0-3 as 2 packed pairs
        ulonglong2 wB = wp[1];        // rows 4-7
        ulonglong2 wC = wp[2];        // rows 8-11
        ulonglong2 wD = wp[3];        // rows 12-15
        ull h2 = pk2f(hc);
        ffma2(acc[0], wA.x, h2); ffma2(acc[1], wA.y, h2);
        ffma2(acc[2], wB.x, h2); ffma2(acc[3], wB.y, h2);
        ffma2(acc[4], wC.x, h2); ffma2(acc[5], wC.y, h2);
        ffma2(acc[6], wD.x, h2); ffma2(acc[7], wD.y, h2);
    }
}

__device__ __forceinline__ void storep3(float* pbuf, ull (&acc)[8], int kg, int b) {
    float* base = &pbuf[(kg * 64 + b) * PPAD];
#pragma unroll
    for (int rp = 0; rp < 8; rp++)
        *(ull*)(base + rp * 2) = acc[rp];
}

__global__ void __launch_bounds__(NTHR, 1) lstm_rec(const float* __restrict__ Whh0,
                                                    const float* __restrict__ Wih1,
                                                    const float* __restrict__ Whh1,
                                                    const float* __restrict__ b1) {
    extern __shared__ float sm[];
    float* wT0  = sm + SM_WT0;
    float* wT1  = sm + SM_WT1;
    float* pbuf = sm + SM_PBUF;

    const int tid = threadIdx.x;
    const int u0  = blockIdx.x * 4;

    // ---- stage weights once, transposed: wT[k][j], j = unit*4 + gate ----
    for (int idx = tid; idx < 512 * 16; idx += NTHR) {
        int j = idx >> 9, k = idx & 511;
        int row = ((j & 3) << 9) + u0 + (j >> 2);
        wT0[k * 16 + j] = Whh0[row * Hd + k];
    }
    for (int idx = tid; idx < 1024 * 16; idx += NTHR) {
        int j = idx >> 10, k = idx & 1023;
        int row = ((j & 3) << 9) + u0 + (j >> 2);
        wT1[k * 16 + j] = (k < 512) ? Wih1[row * Hd + k] : Whh1[row * Hd + (k - 512)];
    }
    __syncthreads();

    // gemm role
    const int w    = tid >> 5;        // warp
    const int kg   = w & 7;           // k-group (64 k)
    const int bh   = w >> 3;          // batch half
    const int lane = tid & 31;
    const int bgem = bh * 32 + lane;  // this thread's batch in gemm role
    // update role (tid < 256)
    const int uu = tid >> 6;
    const int bb = tid & 63;
    float c0 = 0.f, c1 = 0.f;
    float b1v[4] = {0.f, 0.f, 0.f, 0.f};
    if (tid < 256)
#pragma unroll
        for (int g = 0; g < 4; g++) b1v[g] = b1[(g << 9) + u0 + uu];

    for (int t = 0; t < Tlen; t++) {
        const int p = t & 1;

        float xgv[4] = {0.f, 0.f, 0.f, 0.f};
        if (tid < 256)
#pragma unroll
            for (int g = 0; g < 4; g++)
                xgv[g] = __ldcs(&g_xg[((size_t)t * G4H + (g << 9) + u0 + uu) * Bsz + bb]);

        // ========== phase 1: gates0 partials = Whh0[:, kg-slice] @ h0_prev ==========
        {
            ull acc[8];
#pragma unroll
            for (int a = 0; a < 8; a++) acc[a] = 0ull;
            gemm3<64>(acc, wT0, kg * 64, g_h0 + (p ^ 1) * HB, kg * 64, bgem);
            storep3(pbuf, acc, kg, bgem);
        }
        __syncthreads();
        if (tid < 256) {
            float s[4] = {xgv[0], xgv[1], xgv[2], xgv[3]};
#pragma unroll
            for (int g8 = 0; g8 < 8; g8++) {
                const float* pp = &pbuf[(g8 * 64 + bb) * PPAD + uu * 4];
                float2 v0 = *(const float2*)pp;
                float2 v1 = *(const float2*)(pp + 2);
                s[0] += v0.x; s[1] += v0.y; s[2] += v1.x; s[3] += v1.y;
            }
            c0 = sigm(s[1]) * c0 + sigm(s[0]) * tanh_fast(s[2]);
            float h0n = sigm(s[3]) * tanh_fast(c0);
            g_h0[p * HB + (u0 + uu) * 64 + bb] = h0n;
        }
        __syncthreads();               // h0n stores + pbuf reads complete
        bar_arrive(&g_bar1);           // publish h0(t)

        // ========== phase 2: Whh1 @ h1_prev, then Wih1 @ h0n ==========
        ull acc2[8];
#pragma unroll
        for (int a = 0; a < 8; a++) acc2[a] = 0ull;

        bar_wait(&g_bar2, NCTA * (unsigned)t);
        gemm3<64>(acc2, wT1, 512 + kg * 64, g_h1 + (p ^ 1) * HB, kg * 64, bgem);
        bar_wait(&g_bar1, NCTA * (unsigned)(t + 1));
        gemm3<64>(acc2, wT1, kg * 64, g_h0 + p * HB, kg * 64, bgem);
        storep3(pbuf, acc2, kg, bgem);

        __syncthreads();
        if (tid < 256) {
            float s[4] = {b1v[0], b1v[1], b1v[2], b1v[3]};
#pragma unroll
            for (int g8 = 0; g8 < 8; g8++) {
                const float* pp = &pbuf[(g8 * 64 + bb) * PPAD + uu * 4];
                float2 v0 = *(const float2*)pp;
                float2 v1 = *(const float2*)(pp + 2);
                s[0] += v0.x; s[1] += v0.y; s[2] += v1.x; s[3] += v1.y;
            }
            c1 = sigm(s[1]) * c1 + sigm(s[0]) * tanh_fast(s[2]);
            float h1n = sigm(s[3]) * tanh_fast(c1);
            g_h1[p * HB + (u0 + uu) * 64 + bb] = h1n;
        }
        __syncthreads();               // h1n stores + pbuf reads complete
        bar_arrive(&g_bar2);           // publish h1(t)
    }
}

// =================================================================
// classifier: 1024 threads, k split 8 ways + smem tree
// =================================================================
__global__ void __launch_bounds__(1024) kclf(const float* __restrict__ Wclf,
                                             const float* __restrict__ bclf,
                                             float* __restrict__ out) {
    __shared__ float red[1024];
    const int t  = threadIdx.x;
    const int o  = t & 1;
    const int b  = (t >> 1) & 63;
    const int ks = t >> 7;
    const float* h = g_h1 + HB;       // parity of t=511 is 1
    float s = 0.f;
#pragma unroll 8
    for (int i = 0; i < 64; i++) {
        int k = ks * 64 + i;
        s = fmaf(Wclf[o * Hd + k], h[k * 64 + b], s);
    }
    red[t] = s;
    __syncthreads();
    if (ks == 0) {
        float v = s + bclf[o];
#pragma unroll
        for (int w8 = 1; w8 < 8; w8++) v += red[t + w8 * 128];
        out[b * 2 + o] = v;
    }
}

// =================================================================
extern "C" void kernel_launch(void* const* d_in, const int* in_sizes, int n_in,
                              void* d_out, int out_size) {
    const int*   x    = (const int*)  d_in[0];
    const float* emb  = (const float*)d_in[1];
    const float* Wih0 = (const float*)d_in[2];
    const float* Whh0 = (const float*)d_in[3];
    const float* b0   = (const float*)d_in[4];
    const float* Wih1 = (const float*)d_in[5];
    const float* Whh1 = (const float*)d_in[6];
    const float* b1   = (const float*)d_in[7];
    const float* Wclf = (const float*)d_in[8];
    const float* bclf = (const float*)d_in[9];
    float* out = (float*)d_out;

    cudaFuncSetAttribute(lstm_rec, cudaFuncAttributeMaxDynamicSharedMemorySize, SMEMB);

    kzero<<<256, 256>>>();
    dim3 gA(Tlen, 32);
    kA<<<gA, 256>>>(x, emb, Wih0, b0);
    lstm_rec<<<NCTA, NTHR, SMEMB>>>(Whh0, Wih1, Whh1, b1);
    kclf<<<1, 1024>>>(Wclf, bclf, out);
}